// round 3
// baseline (speedup 1.0000x reference)
#include <cuda_runtime.h>
#include <cuda_bf16.h>

// FlyVisAdExODE: event-driven COBA scatter + AdEx Euler step.
// N = 131072 neurons, E = N*64 = 8388608 edges.
//
// Phase 1 (prep):    per-neuron activity code (0=idle, 1=exc-spike, 2=inh-spike),
//                    zero packed counters. spiked/is_excitatory are 4-byte
//                    (int32 OR float32 — nonzero-u32 test is correct for both).
// Phase 2 (scatter): stream edge_index; for active edges atomically bump a
//                    packed u32 counter at dst (exc count low16, inh count hi16).
//                    Integer atomics => exactly deterministic.
// Phase 3 (update):  ge += Q_ge*cnt_exc, gi += Q_gi*cnt_inh, then full AdEx math.

#define NMAX 131072

__device__ unsigned int  g_cnt[NMAX];
__device__ unsigned char g_code[NMAX];

__global__ void prep_kernel(const unsigned int* __restrict__ spiked,
                            const unsigned int* __restrict__ is_exc,
                            int n) {
    int i = blockIdx.x * blockDim.x + threadIdx.x;
    if (i < n) {
        g_cnt[i] = 0u;
        // works for both int32 (1/0) and float32 (0x3F800000 / 0x0) encodings
        bool s = spiked[i] != 0u;
        bool e = is_exc[i] != 0u;
        g_code[i] = s ? (e ? (unsigned char)1 : (unsigned char)2)
                      : (unsigned char)0;
    }
}

// Each thread handles 4 consecutive edges via an int4 load of src.
// dst is loaded ONLY for active edges (predicated) — warps whose 128-edge
// span has no active source skip those dst cache lines entirely.
__global__ void scatter_kernel(const int* __restrict__ src,
                               const int* __restrict__ dst,
                               int e4) {
    int t = blockIdx.x * blockDim.x + threadIdx.x;
    if (t >= e4) return;
    int4 s = reinterpret_cast<const int4*>(src)[t];
    int base = t << 2;

    unsigned char c0 = g_code[s.x];
    unsigned char c1 = g_code[s.y];
    unsigned char c2 = g_code[s.z];
    unsigned char c3 = g_code[s.w];

    if (c0) { int d = __ldg(dst + base + 0); atomicAdd(&g_cnt[d], c0 == 1 ? 1u : 65536u); }
    if (c1) { int d = __ldg(dst + base + 1); atomicAdd(&g_cnt[d], c1 == 1 ? 1u : 65536u); }
    if (c2) { int d = __ldg(dst + base + 2); atomicAdd(&g_cnt[d], c2 == 1 ? 1u : 65536u); }
    if (c3) { int d = __ldg(dst + base + 3); atomicAdd(&g_cnt[d], c3 == 1 ? 1u : 65536u); }
}

struct NeuronParams {
    const float *v, *w, *ge, *gi, *stim, *refr;
    const float *g_L, *delta_T, *v_thresh, *v_rest, *C, *a, *b;
    const float *tau_w, *tau_ge, *tau_gi;
    const float *E_ge, *E_gi, *I_bias, *stim_scale, *Q_ge, *Q_gi;
    const float *v_cut, *v_reset, *t_refrac;
    const float *dt_ptr;
    float* out;
    int n;
};

__global__ void update_kernel(NeuronParams p) {
    int i = blockIdx.x * blockDim.x + threadIdx.x;
    if (i >= p.n) return;

    const float dt = __ldg(p.dt_ptr);

    // 1. apply spike propagation via packed counts
    unsigned int cnt = g_cnt[i];
    float ge = p.ge[i] + p.Q_ge[i] * (float)(cnt & 0xFFFFu);
    float gi = p.gi[i] + p.Q_gi[i] * (float)(cnt >> 16);

    float v  = p.v[i];
    float w  = p.w[i];
    float gL = p.g_L[i];
    float dT = p.delta_T[i];
    float vr = p.v_rest[i];

    // 2. derivatives (post-propagation conductances, pre-Euler voltage)
    float I  = p.I_bias[i] + p.stim_scale[i] * p.stim[i]
             + ge * (p.E_ge[i] - v) + gi * (p.E_gi[i] - v);
    float ex = gL * dT * expf(fminf((v - p.v_thresh[i]) / dT, 20.0f));
    float dv = (-gL * (v - vr) + ex - w + I) / p.C[i];
    float dw = (-w + p.a[i] * (v - vr)) / p.tau_w[i];

    // 3. Euler step (voltage frozen while refractory)
    float refr = p.refr[i];
    float vn = (refr <= 0.0f) ? (v + dv * dt) : v;
    float wn = w + dw * dt;
    ge = ge - (ge / p.tau_ge[i]) * dt;
    gi = gi - (gi / p.tau_gi[i]) * dt;

    // 4. spike detection + reset
    bool spk = vn > p.v_cut[i];
    vn = spk ? p.v_reset[i] : vn;
    wn = spk ? (wn + p.b[i]) : wn;
    float rf = (spk ? p.t_refrac[i] : refr) - dt;

    // 5. outputs: [v, w, ge, gi, refrac, spk] each length n
    const int n = p.n;
    float* out = p.out;
    out[i]         = vn;
    out[n + i]     = wn;
    out[2 * n + i] = ge;
    out[3 * n + i] = gi;
    out[4 * n + i] = rf;
    out[5 * n + i] = spk ? 1.0f : 0.0f;
}

extern "C" void kernel_launch(void* const* d_in, const int* in_sizes, int n_in,
                              void* d_out, int out_size) {
    // metadata order (reference signature order):
    // 0 voltage, 1 adapt_current, 2 ge, 3 gi, 4 stimulus, 5 refractory_counter,
    // 6 g_L, 7 delta_T, 8 v_thresh, 9 v_rest, 10 C, 11 a, 12 b, 13 tau_w,
    // 14 tau_ge, 15 tau_gi, 16 E_ge, 17 E_gi, 18 I_bias, 19 stim_scale,
    // 20 Q_ge, 21 Q_gi, 22 v_cut, 23 v_reset, 24 t_refrac,
    // 25 spiked(4-byte), 26 is_excitatory(4-byte), 27 edge_index(int32, 2E), 28 dt(f32 scalar)
    const int n = in_sizes[0];
    const int E = in_sizes[27] / 2;

    const unsigned int* spiked = (const unsigned int*)d_in[25];
    const unsigned int* is_exc = (const unsigned int*)d_in[26];
    const int* edge = (const int*)d_in[27];
    const int* src = edge;
    const int* dst = edge + E;

    const int TPB = 256;

    // Phase 1: codes + zero counters
    prep_kernel<<<(n + TPB - 1) / TPB, TPB>>>(spiked, is_exc, n);

    // Phase 2: scatter (4 edges per thread)
    int e4 = E / 4;                       // E = 8388608, divisible by 4
    scatter_kernel<<<(e4 + TPB - 1) / TPB, TPB>>>(src, dst, e4);

    // Phase 3: neuron update
    NeuronParams p;
    p.v = (const float*)d_in[0];   p.w = (const float*)d_in[1];
    p.ge = (const float*)d_in[2];  p.gi = (const float*)d_in[3];
    p.stim = (const float*)d_in[4]; p.refr = (const float*)d_in[5];
    p.g_L = (const float*)d_in[6]; p.delta_T = (const float*)d_in[7];
    p.v_thresh = (const float*)d_in[8]; p.v_rest = (const float*)d_in[9];
    p.C = (const float*)d_in[10];  p.a = (const float*)d_in[11];
    p.b = (const float*)d_in[12];  p.tau_w = (const float*)d_in[13];
    p.tau_ge = (const float*)d_in[14]; p.tau_gi = (const float*)d_in[15];
    p.E_ge = (const float*)d_in[16]; p.E_gi = (const float*)d_in[17];
    p.I_bias = (const float*)d_in[18]; p.stim_scale = (const float*)d_in[19];
    p.Q_ge = (const float*)d_in[20]; p.Q_gi = (const float*)d_in[21];
    p.v_cut = (const float*)d_in[22]; p.v_reset = (const float*)d_in[23];
    p.t_refrac = (const float*)d_in[24];
    p.dt_ptr = (const float*)d_in[28];
    p.out = (float*)d_out;
    p.n = n;

    update_kernel<<<(n + TPB - 1) / TPB, TPB>>>(p);
}

// round 4
// speedup vs baseline: 1.2280x; 1.2280x over previous
#include <cuda_runtime.h>
#include <cuda_bf16.h>

// FlyVisAdExODE: event-driven COBA scatter + AdEx Euler step.
// N = 131072 neurons, E = N*64 = 8388608 edges.
//
// R3 redesign: the per-edge activity gather was L1tex-wavefront-bound
// (random byte gather over 128KB => ~32 wavefronts/warp-load). Now codes are
// 2-bit packed (16/word, 32KB total), staged into SHARED memory by persistent
// blocks; gathers are LDS with ~4-way expected bank conflicts. dst is loaded
// only when one of the thread's 4 edges is active (saves ~2/3 of dst DRAM
// sectors at 5% spike rate). Integer packed-count atomics stay deterministic.

#define NMAX   131072
#define NWORDS (NMAX / 16)   // 8192 u32 words of 2-bit codes = 32KB

__device__ unsigned int g_cnt[NMAX];
__device__ unsigned int g_tbl[NWORDS];

// ---------------------------------------------------------------------------
// Phase 1: zero counters (uint4 stores) + build 2-bit code table.
// code: 0 = idle, 1 = exc spike, 2 = inh spike.
// spiked / is_excitatory are 4-byte (int32 or float32): nonzero-u32 test works
// for both.
// ---------------------------------------------------------------------------
__global__ void prep_kernel(const uint4* __restrict__ spiked,
                            const uint4* __restrict__ is_exc) {
    int t = blockIdx.x * blockDim.x + threadIdx.x;   // 32768 threads

    // zero 4 counters per thread (vectorized)
    reinterpret_cast<uint4*>(g_cnt)[t] = make_uint4(0u, 0u, 0u, 0u);

    // first NWORDS threads each build one 16-neuron code word
    if (t < NWORDS) {
        unsigned word = 0u;
        int base = t * 4;                            // uint4 index; 16 neurons
        #pragma unroll
        for (int q = 0; q < 4; q++) {
            uint4 s = spiked[base + q];
            uint4 e = is_exc[base + q];
            unsigned c0 = s.x ? (e.x ? 1u : 2u) : 0u;
            unsigned c1 = s.y ? (e.y ? 1u : 2u) : 0u;
            unsigned c2 = s.z ? (e.z ? 1u : 2u) : 0u;
            unsigned c3 = s.w ? (e.w ? 1u : 2u) : 0u;
            word |= (c0 | (c1 << 2) | (c2 << 4) | (c3 << 6)) << (q * 8);
        }
        g_tbl[t] = word;
    }
}

// ---------------------------------------------------------------------------
// Phase 2: persistent scatter. Grid-stride over E/4 int4 chunks of src.
// Shared-memory 2-bit table gather; predicated int4 dst load; packed atomics.
// ---------------------------------------------------------------------------
__global__ __launch_bounds__(512, 4)
void scatter_kernel(const int4* __restrict__ src4,
                    const int*  __restrict__ dst,
                    int e4) {
    __shared__ unsigned tbl[NWORDS];
    for (int j = threadIdx.x; j < NWORDS; j += 512)
        tbl[j] = g_tbl[j];
    __syncthreads();

    const int stride = gridDim.x * blockDim.x;
    for (int t = blockIdx.x * blockDim.x + threadIdx.x; t < e4; t += stride) {
        int4 s = src4[t];

        unsigned c0 = (tbl[s.x >> 4] >> ((s.x & 15) << 1)) & 3u;
        unsigned c1 = (tbl[s.y >> 4] >> ((s.y & 15) << 1)) & 3u;
        unsigned c2 = (tbl[s.z >> 4] >> ((s.z & 15) << 1)) & 3u;
        unsigned c3 = (tbl[s.w >> 4] >> ((s.w & 15) << 1)) & 3u;

        if (c0 | c1 | c2 | c3) {
            int4 d = __ldg(reinterpret_cast<const int4*>(dst) + t);
            // addend: code 1 -> +1 (exc, low16), code 2 -> +65536 (inh, hi16)
            if (c0) atomicAdd(&g_cnt[d.x], (c0 & 1u) | ((c0 & 2u) << 15));
            if (c1) atomicAdd(&g_cnt[d.y], (c1 & 1u) | ((c1 & 2u) << 15));
            if (c2) atomicAdd(&g_cnt[d.z], (c2 & 1u) | ((c2 & 2u) << 15));
            if (c3) atomicAdd(&g_cnt[d.w], (c3 & 1u) | ((c3 & 2u) << 15));
        }
    }
}

// ---------------------------------------------------------------------------
// Phase 3: AdEx Euler update.
// ---------------------------------------------------------------------------
struct NeuronParams {
    const float *v, *w, *ge, *gi, *stim, *refr;
    const float *g_L, *delta_T, *v_thresh, *v_rest, *C, *a, *b;
    const float *tau_w, *tau_ge, *tau_gi;
    const float *E_ge, *E_gi, *I_bias, *stim_scale, *Q_ge, *Q_gi;
    const float *v_cut, *v_reset, *t_refrac;
    const float *dt_ptr;
    float* out;
    int n;
};

__global__ void update_kernel(NeuronParams p) {
    int i = blockIdx.x * blockDim.x + threadIdx.x;
    if (i >= p.n) return;

    const float dt = __ldg(p.dt_ptr);

    unsigned int cnt = g_cnt[i];
    float ge = p.ge[i] + p.Q_ge[i] * (float)(cnt & 0xFFFFu);
    float gi = p.gi[i] + p.Q_gi[i] * (float)(cnt >> 16);

    float v  = p.v[i];
    float w  = p.w[i];
    float gL = p.g_L[i];
    float dT = p.delta_T[i];
    float vr = p.v_rest[i];

    float I  = p.I_bias[i] + p.stim_scale[i] * p.stim[i]
             + ge * (p.E_ge[i] - v) + gi * (p.E_gi[i] - v);
    float ex = gL * dT * expf(fminf((v - p.v_thresh[i]) / dT, 20.0f));
    float dv = (-gL * (v - vr) + ex - w + I) / p.C[i];
    float dw = (-w + p.a[i] * (v - vr)) / p.tau_w[i];

    float refr = p.refr[i];
    float vn = (refr <= 0.0f) ? (v + dv * dt) : v;
    float wn = w + dw * dt;
    ge = ge - (ge / p.tau_ge[i]) * dt;
    gi = gi - (gi / p.tau_gi[i]) * dt;

    bool spk = vn > p.v_cut[i];
    vn = spk ? p.v_reset[i] : vn;
    wn = spk ? (wn + p.b[i]) : wn;
    float rf = (spk ? p.t_refrac[i] : refr) - dt;

    const int n = p.n;
    float* out = p.out;
    out[i]         = vn;
    out[n + i]     = wn;
    out[2 * n + i] = ge;
    out[3 * n + i] = gi;
    out[4 * n + i] = rf;
    out[5 * n + i] = spk ? 1.0f : 0.0f;
}

extern "C" void kernel_launch(void* const* d_in, const int* in_sizes, int n_in,
                              void* d_out, int out_size) {
    const int n = in_sizes[0];          // 131072
    const int E = in_sizes[27] / 2;     // 8388608

    const int* edge = (const int*)d_in[27];
    const int4* src4 = (const int4*)edge;
    const int* dst = edge + E;

    // Phase 1: 32768 threads (each zeroes 4 counters; first 8192 build table)
    prep_kernel<<<(n / 4 + 255) / 256, 256>>>((const uint4*)d_in[25],
                                              (const uint4*)d_in[26]);

    // Phase 2: persistent scatter, 148 SMs x 4 blocks x 512 threads
    int e4 = E / 4;
    scatter_kernel<<<148 * 4, 512>>>(src4, dst, e4);

    // Phase 3: neuron update
    NeuronParams p;
    p.v = (const float*)d_in[0];   p.w = (const float*)d_in[1];
    p.ge = (const float*)d_in[2];  p.gi = (const float*)d_in[3];
    p.stim = (const float*)d_in[4]; p.refr = (const float*)d_in[5];
    p.g_L = (const float*)d_in[6]; p.delta_T = (const float*)d_in[7];
    p.v_thresh = (const float*)d_in[8]; p.v_rest = (const float*)d_in[9];
    p.C = (const float*)d_in[10];  p.a = (const float*)d_in[11];
    p.b = (const float*)d_in[12];  p.tau_w = (const float*)d_in[13];
    p.tau_ge = (const float*)d_in[14]; p.tau_gi = (const float*)d_in[15];
    p.E_ge = (const float*)d_in[16]; p.E_gi = (const float*)d_in[17];
    p.I_bias = (const float*)d_in[18]; p.stim_scale = (const float*)d_in[19];
    p.Q_ge = (const float*)d_in[20]; p.Q_gi = (const float*)d_in[21];
    p.v_cut = (const float*)d_in[22]; p.v_reset = (const float*)d_in[23];
    p.t_refrac = (const float*)d_in[24];
    p.dt_ptr = (const float*)d_in[28];
    p.out = (float*)d_out;
    p.n = n;

    update_kernel<<<(n + 255) / 256, 256>>>(p);
}

// round 7
// speedup vs baseline: 1.2434x; 1.0125x over previous
#include <cuda_runtime.h>
#include <cuda_bf16.h>

// FlyVisAdExODE: event-driven COBA scatter + AdEx Euler step.
// N = 131072 neurons, E = N*64 = 8388608 edges.
//
// R4: (1) prep rebuilt with ballot + 16-bit Morton interleave — full-width
// parallelism, coalesced loads (was: 8192 threads x serial 8-load chains,
// 5 us). (2) scatter main loop unrolled x4 with front-batched src4 loads to
// raise per-thread MLP from ~1 to 4. Codes stay 2-bit packed (32KB) in smem;
// dst loaded only for threads with >=1 active edge; packed int atomics.

#define NMAX   131072
#define NWORDS (NMAX / 16)   // 8192 u32 words of 2-bit codes = 32KB

__device__ unsigned int g_cnt[NMAX];
__device__ unsigned int g_tbl[NWORDS];

// spread 16 bits to even bit positions (Morton half-interleave)
__device__ __forceinline__ unsigned spread16(unsigned x) {
    x = (x | (x << 8)) & 0x00FF00FFu;
    x = (x | (x << 4)) & 0x0F0F0F0Fu;
    x = (x | (x << 2)) & 0x33333333u;
    x = (x | (x << 1)) & 0x55555555u;
    return x;
}

// ---------------------------------------------------------------------------
// Phase 1: one thread per neuron. Zero counter; ballot spike/exc masks;
// lanes 0..1 write the warp's two 16-neuron code words.
// code: bit0 = exc spike (+1 to low16), bit1 = inh spike (+65536 via <<15).
// spiked / is_excitatory are 4-byte (int32 or float32): nonzero-u32 is correct
// for both encodings.
// ---------------------------------------------------------------------------
__global__ void prep_kernel(const unsigned* __restrict__ spiked,
                            const unsigned* __restrict__ is_exc) {
    int i = blockIdx.x * blockDim.x + threadIdx.x;   // exactly N threads
    g_cnt[i] = 0u;

    unsigned s = spiked[i];
    unsigned e = is_exc[i];
    unsigned m_exc = __ballot_sync(0xFFFFFFFFu, s && e);
    unsigned m_inh = __ballot_sync(0xFFFFFFFFu, s && !e);

    int lane = threadIdx.x & 31;
    if (lane < 2) {
        unsigned hx = (m_exc >> (lane << 4)) & 0xFFFFu;
        unsigned hi = (m_inh >> (lane << 4)) & 0xFFFFu;
        unsigned w = spread16(hx) | (spread16(hi) << 1);
        g_tbl[((i >> 5) << 1) + lane] = w;
    }
}

// ---------------------------------------------------------------------------
// Phase 2: persistent scatter over E/4 int4 chunks, unroll x4 (front-batched
// loads => MLP 4). Shared 2-bit table gather; predicated int4 dst load.
// ---------------------------------------------------------------------------
__device__ __forceinline__ void do_chunk(const unsigned* tbl,
                                         const int* __restrict__ dst,
                                         int4 s, int t) {
    unsigned c0 = (tbl[s.x >> 4] >> ((s.x & 15) << 1)) & 3u;
    unsigned c1 = (tbl[s.y >> 4] >> ((s.y & 15) << 1)) & 3u;
    unsigned c2 = (tbl[s.z >> 4] >> ((s.z & 15) << 1)) & 3u;
    unsigned c3 = (tbl[s.w >> 4] >> ((s.w & 15) << 1)) & 3u;
    if (c0 | c1 | c2 | c3) {
        int4 d = __ldg(reinterpret_cast<const int4*>(dst) + t);
        if (c0) atomicAdd(&g_cnt[d.x], (c0 & 1u) | ((c0 & 2u) << 15));
        if (c1) atomicAdd(&g_cnt[d.y], (c1 & 1u) | ((c1 & 2u) << 15));
        if (c2) atomicAdd(&g_cnt[d.z], (c2 & 1u) | ((c2 & 2u) << 15));
        if (c3) atomicAdd(&g_cnt[d.w], (c3 & 1u) | ((c3 & 2u) << 15));
    }
}

__global__ __launch_bounds__(512, 4)
void scatter_kernel(const int4* __restrict__ src4,
                    const int*  __restrict__ dst,
                    int e4) {
    __shared__ unsigned tbl[NWORDS];
    for (int j = threadIdx.x; j < NWORDS; j += 512)
        tbl[j] = g_tbl[j];
    __syncthreads();

    const int T = gridDim.x * blockDim.x;
    int t = blockIdx.x * blockDim.x + threadIdx.x;

    // unrolled x4: batch the four independent src4 loads up front
    for (; t + 3 * T < e4; t += 4 * T) {
        int4 s0 = src4[t];
        int4 s1 = src4[t + T];
        int4 s2 = src4[t + 2 * T];
        int4 s3 = src4[t + 3 * T];
        do_chunk(tbl, dst, s0, t);
        do_chunk(tbl, dst, s1, t + T);
        do_chunk(tbl, dst, s2, t + 2 * T);
        do_chunk(tbl, dst, s3, t + 3 * T);
    }
    for (; t < e4; t += T)
        do_chunk(tbl, dst, src4[t], t);
}

// ---------------------------------------------------------------------------
// Phase 3: AdEx Euler update.
// ---------------------------------------------------------------------------
struct NeuronParams {
    const float *v, *w, *ge, *gi, *stim, *refr;
    const float *g_L, *delta_T, *v_thresh, *v_rest, *C, *a, *b;
    const float *tau_w, *tau_ge, *tau_gi;
    const float *E_ge, *E_gi, *I_bias, *stim_scale, *Q_ge, *Q_gi;
    const float *v_cut, *v_reset, *t_refrac;
    const float *dt_ptr;
    float* out;
    int n;
};

__global__ void update_kernel(NeuronParams p) {
    int i = blockIdx.x * blockDim.x + threadIdx.x;
    if (i >= p.n) return;

    const float dt = __ldg(p.dt_ptr);

    unsigned int cnt = g_cnt[i];
    float ge = p.ge[i] + p.Q_ge[i] * (float)(cnt & 0xFFFFu);
    float gi = p.gi[i] + p.Q_gi[i] * (float)(cnt >> 16);

    float v  = p.v[i];
    float w  = p.w[i];
    float gL = p.g_L[i];
    float dT = p.delta_T[i];
    float vr = p.v_rest[i];

    float I  = p.I_bias[i] + p.stim_scale[i] * p.stim[i]
             + ge * (p.E_ge[i] - v) + gi * (p.E_gi[i] - v);
    float ex = gL * dT * expf(fminf((v - p.v_thresh[i]) / dT, 20.0f));
    float dv = (-gL * (v - vr) + ex - w + I) / p.C[i];
    float dw = (-w + p.a[i] * (v - vr)) / p.tau_w[i];

    float refr = p.refr[i];
    float vn = (refr <= 0.0f) ? (v + dv * dt) : v;
    float wn = w + dw * dt;
    ge = ge - (ge / p.tau_ge[i]) * dt;
    gi = gi - (gi / p.tau_gi[i]) * dt;

    bool spk = vn > p.v_cut[i];
    vn = spk ? p.v_reset[i] : vn;
    wn = spk ? (wn + p.b[i]) : wn;
    float rf = (spk ? p.t_refrac[i] : refr) - dt;

    const int n = p.n;
    float* out = p.out;
    out[i]         = vn;
    out[n + i]     = wn;
    out[2 * n + i] = ge;
    out[3 * n + i] = gi;
    out[4 * n + i] = rf;
    out[5 * n + i] = spk ? 1.0f : 0.0f;
}

extern "C" void kernel_launch(void* const* d_in, const int* in_sizes, int n_in,
                              void* d_out, int out_size) {
    const int n = in_sizes[0];          // 131072
    const int E = in_sizes[27] / 2;     // 8388608

    const int* edge = (const int*)d_in[27];
    const int4* src4 = (const int4*)edge;
    const int* dst = edge + E;

    // Phase 1: one thread per neuron
    prep_kernel<<<n / 256, 256>>>((const unsigned*)d_in[25],
                                  (const unsigned*)d_in[26]);

    // Phase 2: persistent scatter, 148 SMs x 4 blocks x 512 threads
    int e4 = E / 4;
    scatter_kernel<<<148 * 4, 512>>>(src4, dst, e4);

    // Phase 3: neuron update
    NeuronParams p;
    p.v = (const float*)d_in[0];   p.w = (const float*)d_in[1];
    p.ge = (const float*)d_in[2];  p.gi = (const float*)d_in[3];
    p.stim = (const float*)d_in[4]; p.refr = (const float*)d_in[5];
    p.g_L = (const float*)d_in[6]; p.delta_T = (const float*)d_in[7];
    p.v_thresh = (const float*)d_in[8]; p.v_rest = (const float*)d_in[9];
    p.C = (const float*)d_in[10];  p.a = (const float*)d_in[11];
    p.b = (const float*)d_in[12];  p.tau_w = (const float*)d_in[13];
    p.tau_ge = (const float*)d_in[14]; p.tau_gi = (const float*)d_in[15];
    p.E_ge = (const float*)d_in[16]; p.E_gi = (const float*)d_in[17];
    p.I_bias = (const float*)d_in[18]; p.stim_scale = (const float*)d_in[19];
    p.Q_ge = (const float*)d_in[20]; p.Q_gi = (const float*)d_in[21];
    p.v_cut = (const float*)d_in[22]; p.v_reset = (const float*)d_in[23];
    p.t_refrac = (const float*)d_in[24];
    p.dt_ptr = (const float*)d_in[28];
    p.out = (float*)d_out;
    p.n = n;

    update_kernel<<<(n + 255) / 256, 256>>>(p);
}

// round 8
// speedup vs baseline: 1.3649x; 1.0977x over previous
#include <cuda_runtime.h>
#include <cuda_bf16.h>

// FlyVisAdExODE: event-driven COBA scatter + AdEx Euler step.
// N = 131072 neurons, E = N*64 = 8388608 edges.
//
// R5: scatter is ISSUE-bound, not memory-bound (whole working set is
// L2-resident across graph replays; MLP unroll was neutral). Cut
// instructions/edge: byte-granular activity code table (128KB) in dynamic
// smem => the activity gather is ONE LDS.U8 with the source index as the
// address (no shift/mask extraction). Codes: 0 idle, 1 exc, 2 inh.
// Packed u32 counter atomics (exc low16 / inh hi16) stay deterministic.

#define NMAX 131072

__device__ unsigned int  g_cnt[NMAX];
__device__ unsigned char g_code[NMAX];

// ---------------------------------------------------------------------------
// Phase 1: one thread per neuron. Zero counter, write byte code.
// spiked / is_excitatory are 4-byte (int32 or float32): nonzero-u32 test is
// correct for both encodings.
// ---------------------------------------------------------------------------
__global__ void prep_kernel(const unsigned* __restrict__ spiked,
                            const unsigned* __restrict__ is_exc) {
    int i = blockIdx.x * blockDim.x + threadIdx.x;   // exactly N threads
    g_cnt[i] = 0u;
    unsigned s = spiked[i];
    unsigned e = is_exc[i];
    g_code[i] = s ? (e ? (unsigned char)1 : (unsigned char)2)
                  : (unsigned char)0;
}

// ---------------------------------------------------------------------------
// Phase 2: persistent scatter, one 1024-thread block per SM, 128KB smem byte
// table. Grid-stride over E/4 int4 chunks, unroll x2.
// ---------------------------------------------------------------------------
__device__ __forceinline__ void do_chunk(const unsigned char* tbl,
                                         const int* __restrict__ dst,
                                         int4 s, int t) {
    unsigned c0 = tbl[s.x];
    unsigned c1 = tbl[s.y];
    unsigned c2 = tbl[s.z];
    unsigned c3 = tbl[s.w];
    if (c0 | c1 | c2 | c3) {
        int4 d = __ldg(reinterpret_cast<const int4*>(dst) + t);
        if (c0) atomicAdd(&g_cnt[d.x], (c0 & 1u) | ((c0 & 2u) << 15));
        if (c1) atomicAdd(&g_cnt[d.y], (c1 & 1u) | ((c1 & 2u) << 15));
        if (c2) atomicAdd(&g_cnt[d.z], (c2 & 1u) | ((c2 & 2u) << 15));
        if (c3) atomicAdd(&g_cnt[d.w], (c3 & 1u) | ((c3 & 2u) << 15));
    }
}

__global__ __launch_bounds__(1024, 1)
void scatter_kernel(const int4* __restrict__ src4,
                    const int*  __restrict__ dst,
                    int e4) {
    extern __shared__ unsigned char tbl[];          // 131072 bytes

    // stage byte table from L2 (g_code) into smem, uint4-wide
    {
        const uint4* gc = reinterpret_cast<const uint4*>(g_code);
        uint4* st = reinterpret_cast<uint4*>(tbl);
        #pragma unroll
        for (int j = 0; j < 8; j++)
            st[threadIdx.x + j * 1024] = gc[threadIdx.x + j * 1024];
    }
    __syncthreads();

    const int T = gridDim.x * blockDim.x;
    int t = blockIdx.x * blockDim.x + threadIdx.x;

    for (; t + T < e4; t += 2 * T) {
        int4 s0 = src4[t];
        int4 s1 = src4[t + T];
        do_chunk(tbl, dst, s0, t);
        do_chunk(tbl, dst, s1, t + T);
    }
    for (; t < e4; t += T)
        do_chunk(tbl, dst, src4[t], t);
}

// ---------------------------------------------------------------------------
// Phase 3: AdEx Euler update.
// ---------------------------------------------------------------------------
struct NeuronParams {
    const float *v, *w, *ge, *gi, *stim, *refr;
    const float *g_L, *delta_T, *v_thresh, *v_rest, *C, *a, *b;
    const float *tau_w, *tau_ge, *tau_gi;
    const float *E_ge, *E_gi, *I_bias, *stim_scale, *Q_ge, *Q_gi;
    const float *v_cut, *v_reset, *t_refrac;
    const float *dt_ptr;
    float* out;
    int n;
};

__global__ void update_kernel(NeuronParams p) {
    int i = blockIdx.x * blockDim.x + threadIdx.x;
    if (i >= p.n) return;

    const float dt = __ldg(p.dt_ptr);

    unsigned int cnt = g_cnt[i];
    float ge = p.ge[i] + p.Q_ge[i] * (float)(cnt & 0xFFFFu);
    float gi = p.gi[i] + p.Q_gi[i] * (float)(cnt >> 16);

    float v  = p.v[i];
    float w  = p.w[i];
    float gL = p.g_L[i];
    float dT = p.delta_T[i];
    float vr = p.v_rest[i];

    float I  = p.I_bias[i] + p.stim_scale[i] * p.stim[i]
             + ge * (p.E_ge[i] - v) + gi * (p.E_gi[i] - v);
    float ex = gL * dT * expf(fminf((v - p.v_thresh[i]) / dT, 20.0f));
    float dv = (-gL * (v - vr) + ex - w + I) / p.C[i];
    float dw = (-w + p.a[i] * (v - vr)) / p.tau_w[i];

    float refr = p.refr[i];
    float vn = (refr <= 0.0f) ? (v + dv * dt) : v;
    float wn = w + dw * dt;
    ge = ge - (ge / p.tau_ge[i]) * dt;
    gi = gi - (gi / p.tau_gi[i]) * dt;

    bool spk = vn > p.v_cut[i];
    vn = spk ? p.v_reset[i] : vn;
    wn = spk ? (wn + p.b[i]) : wn;
    float rf = (spk ? p.t_refrac[i] : refr) - dt;

    const int n = p.n;
    float* out = p.out;
    out[i]         = vn;
    out[n + i]     = wn;
    out[2 * n + i] = ge;
    out[3 * n + i] = gi;
    out[4 * n + i] = rf;
    out[5 * n + i] = spk ? 1.0f : 0.0f;
}

extern "C" void kernel_launch(void* const* d_in, const int* in_sizes, int n_in,
                              void* d_out, int out_size) {
    const int n = in_sizes[0];          // 131072
    const int E = in_sizes[27] / 2;     // 8388608

    const int* edge = (const int*)d_in[27];
    const int4* src4 = (const int4*)edge;
    const int* dst = edge + E;

    // allow 128KB dynamic smem for the scatter (host-side attr, capture-safe)
    static bool attr_done = false;
    if (!attr_done) {
        cudaFuncSetAttribute(scatter_kernel,
                             cudaFuncAttributeMaxDynamicSharedMemorySize,
                             NMAX);
        attr_done = true;
    }

    // Phase 1: one thread per neuron
    prep_kernel<<<n / 256, 256>>>((const unsigned*)d_in[25],
                                  (const unsigned*)d_in[26]);

    // Phase 2: persistent scatter, 148 blocks x 1024 threads, 128KB smem
    int e4 = E / 4;
    scatter_kernel<<<148, 1024, NMAX>>>(src4, dst, e4);

    // Phase 3: neuron update
    NeuronParams p;
    p.v = (const float*)d_in[0];   p.w = (const float*)d_in[1];
    p.ge = (const float*)d_in[2];  p.gi = (const float*)d_in[3];
    p.stim = (const float*)d_in[4]; p.refr = (const float*)d_in[5];
    p.g_L = (const float*)d_in[6]; p.delta_T = (const float*)d_in[7];
    p.v_thresh = (const float*)d_in[8]; p.v_rest = (const float*)d_in[9];
    p.C = (const float*)d_in[10];  p.a = (const float*)d_in[11];
    p.b = (const float*)d_in[12];  p.tau_w = (const float*)d_in[13];
    p.tau_ge = (const float*)d_in[14]; p.tau_gi = (const float*)d_in[15];
    p.E_ge = (const float*)d_in[16]; p.E_gi = (const float*)d_in[17];
    p.I_bias = (const float*)d_in[18]; p.stim_scale = (const float*)d_in[19];
    p.Q_ge = (const float*)d_in[20]; p.Q_gi = (const float*)d_in[21];
    p.v_cut = (const float*)d_in[22]; p.v_reset = (const float*)d_in[23];
    p.t_refrac = (const float*)d_in[24];
    p.dt_ptr = (const float*)d_in[28];
    p.out = (float*)d_out;
    p.n = n;

    update_kernel<<<(n + 255) / 256, 256>>>(p);
}

// round 9
// speedup vs baseline: 1.3904x; 1.0187x over previous
#include <cuda_runtime.h>
#include <cuda_bf16.h>

// FlyVisAdExODE: event-driven COBA scatter + AdEx Euler step.
// N = 131072 neurons, E = N*64 = 8388608 edges.
//
// R6: (1) g_cnt zeroing moved into update_kernel (read-then-rezero) — the
// zero-at-entry invariant is established by static zero-init on the first
// call and re-established by every call thereafter. Prep is now a pure
// uint4-vectorized code build (4 neurons/thread, uchar4 store).
// (2) scatter processes 8 edges/iter with ONE combined idle test (66% of
// iterations take the straight-line path). Byte code table (128KB) in smem;
// packed u32 counter atomics (exc low16 / inh hi16) stay deterministic.

#define NMAX 131072

__device__ unsigned int  g_cnt[NMAX];   // zero-initialized at module load
__device__ unsigned char g_code[NMAX];

// ---------------------------------------------------------------------------
// Phase 1: build byte codes. 0 idle, 1 exc spike, 2 inh spike.
// spiked / is_excitatory are 4-byte (int32 or float32): nonzero-u32 test is
// correct for both encodings.
// ---------------------------------------------------------------------------
__global__ void prep_kernel(const uint4* __restrict__ spiked,
                            const uint4* __restrict__ is_exc) {
    int t = blockIdx.x * blockDim.x + threadIdx.x;   // N/4 threads
    uint4 s = spiked[t];
    uint4 e = is_exc[t];
    uchar4 c;
    c.x = s.x ? (e.x ? 1 : 2) : 0;
    c.y = s.y ? (e.y ? 1 : 2) : 0;
    c.z = s.z ? (e.z ? 1 : 2) : 0;
    c.w = s.w ? (e.w ? 1 : 2) : 0;
    reinterpret_cast<uchar4*>(g_code)[t] = c;
}

// ---------------------------------------------------------------------------
// Phase 2: persistent scatter, one 1024-thread block per SM, 128KB smem byte
// table. 8 edges per iteration, single combined idle test.
// ---------------------------------------------------------------------------
__device__ __forceinline__ void emit4(const int* __restrict__ dst, int t,
                                      unsigned c0, unsigned c1,
                                      unsigned c2, unsigned c3) {
    int4 d = __ldg(reinterpret_cast<const int4*>(dst) + t);
    if (c0) atomicAdd(&g_cnt[d.x], (c0 & 1u) | ((c0 & 2u) << 15));
    if (c1) atomicAdd(&g_cnt[d.y], (c1 & 1u) | ((c1 & 2u) << 15));
    if (c2) atomicAdd(&g_cnt[d.z], (c2 & 1u) | ((c2 & 2u) << 15));
    if (c3) atomicAdd(&g_cnt[d.w], (c3 & 1u) | ((c3 & 2u) << 15));
}

__global__ __launch_bounds__(1024, 1)
void scatter_kernel(const int4* __restrict__ src4,
                    const int*  __restrict__ dst,
                    int e4) {
    extern __shared__ unsigned char tbl[];          // 131072 bytes

    // stage byte table from L2 (g_code) into smem, uint4-wide
    {
        const uint4* gc = reinterpret_cast<const uint4*>(g_code);
        uint4* st = reinterpret_cast<uint4*>(tbl);
        #pragma unroll
        for (int j = 0; j < 8; j++)
            st[threadIdx.x + j * 1024] = gc[threadIdx.x + j * 1024];
    }
    __syncthreads();

    const int T = gridDim.x * blockDim.x;
    int t = blockIdx.x * blockDim.x + threadIdx.x;

    for (; t + T < e4; t += 2 * T) {
        int4 s0 = src4[t];
        int4 s1 = src4[t + T];

        unsigned a0 = tbl[s0.x], a1 = tbl[s0.y], a2 = tbl[s0.z], a3 = tbl[s0.w];
        unsigned b0 = tbl[s1.x], b1 = tbl[s1.y], b2 = tbl[s1.z], b3 = tbl[s1.w];

        if ((a0 | a1 | a2 | a3 | b0 | b1 | b2 | b3) != 0u) {
            if (a0 | a1 | a2 | a3) emit4(dst, t,     a0, a1, a2, a3);
            if (b0 | b1 | b2 | b3) emit4(dst, t + T, b0, b1, b2, b3);
        }
    }
    for (; t < e4; t += T) {
        int4 s = src4[t];
        unsigned c0 = tbl[s.x], c1 = tbl[s.y], c2 = tbl[s.z], c3 = tbl[s.w];
        if (c0 | c1 | c2 | c3) emit4(dst, t, c0, c1, c2, c3);
    }
}

// ---------------------------------------------------------------------------
// Phase 3: AdEx Euler update. Reads g_cnt then rezeroes it (maintains the
// zero-at-entry invariant for the next kernel_launch call).
// ---------------------------------------------------------------------------
struct NeuronParams {
    const float *v, *w, *ge, *gi, *stim, *refr;
    const float *g_L, *delta_T, *v_thresh, *v_rest, *C, *a, *b;
    const float *tau_w, *tau_ge, *tau_gi;
    const float *E_ge, *E_gi, *I_bias, *stim_scale, *Q_ge, *Q_gi;
    const float *v_cut, *v_reset, *t_refrac;
    const float *dt_ptr;
    float* out;
    int n;
};

__global__ void update_kernel(NeuronParams p) {
    int i = blockIdx.x * blockDim.x + threadIdx.x;
    if (i >= p.n) return;

    const float dt = __ldg(p.dt_ptr);

    unsigned int cnt = g_cnt[i];
    g_cnt[i] = 0u;                       // re-arm for next launch
    float ge = p.ge[i] + p.Q_ge[i] * (float)(cnt & 0xFFFFu);
    float gi = p.gi[i] + p.Q_gi[i] * (float)(cnt >> 16);

    float v  = p.v[i];
    float w  = p.w[i];
    float gL = p.g_L[i];
    float dT = p.delta_T[i];
    float vr = p.v_rest[i];

    float I  = p.I_bias[i] + p.stim_scale[i] * p.stim[i]
             + ge * (p.E_ge[i] - v) + gi * (p.E_gi[i] - v);
    float ex = gL * dT * expf(fminf((v - p.v_thresh[i]) / dT, 20.0f));
    float dv = (-gL * (v - vr) + ex - w + I) / p.C[i];
    float dw = (-w + p.a[i] * (v - vr)) / p.tau_w[i];

    float refr = p.refr[i];
    float vn = (refr <= 0.0f) ? (v + dv * dt) : v;
    float wn = w + dw * dt;
    ge = ge - (ge / p.tau_ge[i]) * dt;
    gi = gi - (gi / p.tau_gi[i]) * dt;

    bool spk = vn > p.v_cut[i];
    vn = spk ? p.v_reset[i] : vn;
    wn = spk ? (wn + p.b[i]) : wn;
    float rf = (spk ? p.t_refrac[i] : refr) - dt;

    const int n = p.n;
    float* out = p.out;
    out[i]         = vn;
    out[n + i]     = wn;
    out[2 * n + i] = ge;
    out[3 * n + i] = gi;
    out[4 * n + i] = rf;
    out[5 * n + i] = spk ? 1.0f : 0.0f;
}

extern "C" void kernel_launch(void* const* d_in, const int* in_sizes, int n_in,
                              void* d_out, int out_size) {
    const int n = in_sizes[0];          // 131072
    const int E = in_sizes[27] / 2;     // 8388608

    const int* edge = (const int*)d_in[27];
    const int4* src4 = (const int4*)edge;
    const int* dst = edge + E;

    // allow 128KB dynamic smem for the scatter (host-side attr, capture-safe)
    static bool attr_done = false;
    if (!attr_done) {
        cudaFuncSetAttribute(scatter_kernel,
                             cudaFuncAttributeMaxDynamicSharedMemorySize,
                             NMAX);
        attr_done = true;
    }

    // Phase 1: code build, 4 neurons/thread
    prep_kernel<<<n / 4 / 256, 256>>>((const uint4*)d_in[25],
                                      (const uint4*)d_in[26]);

    // Phase 2: persistent scatter, 148 blocks x 1024 threads, 128KB smem
    int e4 = E / 4;
    scatter_kernel<<<148, 1024, NMAX>>>(src4, dst, e4);

    // Phase 3: neuron update (also rezeroes g_cnt)
    update_kernel<<<(n + 255) / 256, 256>>>(
        NeuronParams{
            (const float*)d_in[0],  (const float*)d_in[1],
            (const float*)d_in[2],  (const float*)d_in[3],
            (const float*)d_in[4],  (const float*)d_in[5],
            (const float*)d_in[6],  (const float*)d_in[7],
            (const float*)d_in[8],  (const float*)d_in[9],
            (const float*)d_in[10], (const float*)d_in[11],
            (const float*)d_in[12], (const float*)d_in[13],
            (const float*)d_in[14], (const float*)d_in[15],
            (const float*)d_in[16], (const float*)d_in[17],
            (const float*)d_in[18], (const float*)d_in[19],
            (const float*)d_in[20], (const float*)d_in[21],
            (const float*)d_in[22], (const float*)d_in[23],
            (const float*)d_in[24], (const float*)d_in[28],
            (float*)d_out, n});
}